// round 16
// baseline (speedup 1.0000x reference)
#include <cuda_runtime.h>
#include <cstdint>

#define BB 64
#define NN 500
#define CC 128
#define HH 256
#define GRIDN 128
#define GRIDB 32         // Phase-B blocks (8 output cols each)
#define THREADS 1024
#define XT_STRIDE 68     // xs_t row stride (64 n + 4 pad), float4-aligned, conflict-free
#define WT_STRIDE 10     // wt row stride (8 oc + 2 pad), float2-aligned, conflict-free

// band thresholds squared (0.19^2, 0.21^2)
#define LO2 0.0361f
#define HI2 0.0441f

// Activation ping-pong, TRANSPOSED layout: g_act[p][o * 64 + n]  (o-major)
__device__ __align__(16) float g_act[2][BB * HH];
__device__ unsigned g_count[8];
__device__ volatile unsigned g_sense[8];

// R8 barrier (proven): all threads fence, thread 0 signals/spins. target = #blocks.
__device__ __forceinline__ void grid_barrier(int idx, unsigned target)
{
    __threadfence();
    __syncthreads();
    if (threadIdx.x == 0) {
        unsigned s = g_sense[idx];
        unsigned arrived = atomicAdd(&g_count[idx], 1u);
        if (arrived == target - 1u) {
            g_count[idx] = 0u;
            __threadfence();
            g_sense[idx] = s + 1u;
        } else {
            while (g_sense[idx] == s) { }
        }
    }
    __syncthreads();
}

__device__ __forceinline__ void grid_barrier_arrive(int idx, unsigned target)
{
    __threadfence();
    __syncthreads();
    if (threadIdx.x == 0) {
        unsigned arrived = atomicAdd(&g_count[idx], 1u);
        if (arrived == target - 1u) {
            g_count[idx] = 0u;
            __threadfence();
            g_sense[idx] = g_sense[idx] + 1u;
        }
    }
}

// smem: Phase A: pj4 500*4 | dataS 500*65 | corrS 64 | cnt   (~138 KB)
//       Phase B: xs_t 256*68 | wt 256*10 | dotS 512 | mS 8 | iS 8  (~82 KB)
#define SMEM_FLOATS (4 * NN + NN * 65 + 64 + 8)
#define SMEM_BYTES  (SMEM_FLOATS * 4)

__global__ __launch_bounds__(THREADS, 1)
void mega_kernel(const float* __restrict__ xyz,   // [B,3,N]
                 const float* __restrict__ pts,   // [B,C,N]
                 const float* __restrict__ l3,    // [B,C]
                 const float* __restrict__ temp,  // [B,1,N]
                 const float* __restrict__ w0, const float* __restrict__ b0,
                 const float* __restrict__ g0, const float* __restrict__ e0,
                 const float* __restrict__ w1, const float* __restrict__ b1,
                 const float* __restrict__ g1, const float* __restrict__ e1,
                 const float* __restrict__ w2, const float* __restrict__ b2,
                 const float* __restrict__ g2, const float* __restrict__ e2,
                 const float* __restrict__ w3, const float* __restrict__ b3,
                 const float* __restrict__ g3, const float* __restrict__ e3,
                 const float* __restrict__ w4, const float* __restrict__ b4,
                 float* __restrict__ tc,
                 float* __restrict__ tsys,
                 float* __restrict__ opts,
                 float* __restrict__ ocorr)
{
    extern __shared__ float sm[];
    const int tid  = threadIdx.x;
    const int bid  = blockIdx.x;
    const int warp = tid >> 5;
    const int lane = tid & 31;

    const int b    = bid >> 1;
    const int half = bid & 1;

    // ------------------------------------------------------------------
    // Phase A0: tsys (odd blocks)   [R8 verbatim]
    // ------------------------------------------------------------------
    if (half == 1) {
        float s = (tid < NN) ? temp[b * NN + tid] : 0.0f;
        #pragma unroll
        for (int off = 16; off; off >>= 1) s += __shfl_down_sync(0xffffffffu, s, off);
        if (lane == 0) sm[warp] = s;
        __syncthreads();
        if (tid < 32) {
            float v = (tid < 16) ? sm[tid] : 0.0f;
            #pragma unroll
            for (int off = 8; off; off >>= 1) v += __shfl_down_sync(0xffffffffu, v, off);
            if (tid == 0) tsys[b] = v * (1.0f / (float)NN);
        }
        __syncthreads();
    }

    // ------------------------------------------------------------------
    // Phase A1: passthrough copy (streaming)   [R8 verbatim]
    // ------------------------------------------------------------------
    {
        const float4* s4 = (const float4*)pts;
        float4*       d4 = (float4*)opts;
        const int total4 = (BB * CC * NN) / 4;
        #pragma unroll 2
        for (int i = bid * THREADS + tid; i < total4; i += GRIDN * THREADS)
            __stcs(d4 + i, __ldcs(s4 + i));
    }

    // ------------------------------------------------------------------
    // Phase A2: correlation   [R8 verbatim]
    // ------------------------------------------------------------------
    {
        float4* pj4   = (float4*)sm;
        float*  dataS = sm + 4 * NN;
        float*  corrS = dataS + NN * 65;
        int*    cntS  = (int*)(corrS + 64);

        if (tid < 64) corrS[tid] = 0.0f;
        if (tid == 64) *cntS = 0;

        const float* xb = xyz + (size_t)b * 3 * NN;
        for (int i = tid; i < NN; i += THREADS) {
            float x = xb[i];
            float y = xb[NN + i];
            float z = xb[2 * NN + i];
            pj4[i] = make_float4(x, y, z, x * x + y * y + z * z);
        }

        const float* pb = pts + (size_t)b * CC * NN + (size_t)half * 64 * NN;
        for (int idx = tid; idx < 64 * NN; idx += THREADS) {
            int c = idx / NN;
            int j = idx - c * NN;
            dataS[j * 65 + c] = pb[c * NN + j];
        }
        __syncthreads();

        float corr0 = 0.0f, corr1 = 0.0f;
        int   cnt   = 0;

        for (int i = warp; i < NN; i += 32) {
            const float4 pi = pj4[i];
            const float di0 = dataS[i * 65 + lane];
            const float di1 = dataS[i * 65 + 32 + lane];
            float t0 = 0.0f, t1 = 0.0f;

            const int jb0 = i & ~31;

            {
                const int j = jb0 + lane;
                bool pred = false;
                if (j > i && j < NN) {
                    float4 pj = pj4[j];
                    float dot = pi.x * pj.x + pi.y * pj.y + pi.z * pj.z;
                    float sq  = fabsf(pi.w + pj.w - 2.0f * dot);
                    pred = (sq > LO2) && (sq < HI2);
                }
                unsigned m = __ballot_sync(0xffffffffu, pred);
                cnt += __popc(m);
                while (m) {
                    int jj = jb0 + (__ffs(m) - 1);
                    m &= m - 1;
                    t0 += dataS[jj * 65 + lane];
                    t1 += dataS[jj * 65 + 32 + lane];
                }
            }

            #pragma unroll 2
            for (int jb = jb0 + 32; jb < 480; jb += 32) {
                float4 pj = pj4[jb + lane];
                float dot = pi.x * pj.x + pi.y * pj.y + pi.z * pj.z;
                float sq  = fabsf(pi.w + pj.w - 2.0f * dot);
                bool pred = (sq > LO2) && (sq < HI2);
                unsigned m = __ballot_sync(0xffffffffu, pred);
                cnt += __popc(m);
                while (m) {
                    int jj = jb + (__ffs(m) - 1);
                    m &= m - 1;
                    t0 += dataS[jj * 65 + lane];
                    t1 += dataS[jj * 65 + 32 + lane];
                }
            }

            if (jb0 < 480) {
                const int j = 480 + lane;
                bool pred = false;
                if (j < NN) {
                    float4 pj = pj4[j];
                    float dot = pi.x * pj.x + pi.y * pj.y + pi.z * pj.z;
                    float sq  = fabsf(pi.w + pj.w - 2.0f * dot);
                    pred = (sq > LO2) && (sq < HI2);
                }
                unsigned m = __ballot_sync(0xffffffffu, pred);
                cnt += __popc(m);
                while (m) {
                    int jj = 480 + (__ffs(m) - 1);
                    m &= m - 1;
                    t0 += dataS[jj * 65 + lane];
                    t1 += dataS[jj * 65 + 32 + lane];
                }
            }

            corr0 += t0 * di0;
            corr1 += t1 * di1;
        }

        atomicAdd(&corrS[lane],      corr0);
        atomicAdd(&corrS[32 + lane], corr1);
        if (lane == 0) atomicAdd(cntS, cnt);
        __syncthreads();

        if (tid < 64) {
            float cf = fmaxf((float)(*cntS), 1.0f);
            ocorr[b * CC + half * 64 + tid] = corrS[tid] / cf;
        }
    }

    // Barrier 0: all 128 arrive; only blocks 0..31 continue.
    if (bid >= GRIDB) {
        grid_barrier_arrive(0, GRIDN);
        return;
    }
    grid_barrier(0, GRIDN);

    // ------------------------------------------------------------------
    // Phase B: 4 BN-MLP layers on 32 blocks, 8 output columns per block.
    // k-major transposed tiles; register tile 4n x 2oc, split-k-16.
    // ------------------------------------------------------------------
    {
        float* xs   = sm;                         // 256 x XT_STRIDE (k-major)
        float* wt   = xs + 256 * XT_STRIDE;       // 256 x WT_STRIDE (k-major)
        float* dotS = wt + 256 * WT_STRIDE;       // [8 oc][64 n]
        float* mS   = dotS + 512;                 // 8
        float* iS   = mS + 8;                     // 8

        const float* Wl[4] = {w0, w1, w2, w3};
        const float* Bl[4] = {b0, b1, b2, b3};
        const float* Gl[4] = {g0, g1, g2, g3};
        const float* El[4] = {e0, e1, e2, e3};

        const int o0 = bid * 8;

        for (int l = 0; l < 4; l++) {
            // --- fill xs_t[k][n] ---
            if (l == 0) {
                // from ocorr [n][128] + l3 [n][128]; coalesced LDG, strided STS
                for (int i = tid; i < BB * HH; i += THREADS) {
                    int n = i >> 8, k = i & 255;
                    float v = (k < 128) ? __ldcg(&ocorr[n * 128 + k])
                                        : __ldcg(&l3[n * 128 + (k - 128)]);
                    xs[k * XT_STRIDE + n] = v;
                }
            } else {
                // g_act is [256 o][64 n] — fully coalesced float4 copy
                const float4* src = (const float4*)&g_act[(l + 1) & 1][0];
                for (int i = tid; i < 4096; i += THREADS) {
                    float4 v = __ldcg(src + i);
                    int k  = i >> 4;
                    int n4 = (i & 15) << 2;
                    *(float4*)&xs[k * XT_STRIDE + n4] = v;
                }
            }
            // --- fill wt[k][oc] from W rows o0..o0+7 (coalesced over k) ---
            for (int i = tid; i < 8 * HH; i += THREADS) {
                int oc = i >> 8, k = i & 255;
                wt[k * WT_STRIDE + oc] = Wl[l][(size_t)(o0 + oc) * HH + k];
            }
            __syncthreads();

            // --- dots: 64 tiles (4n x 2oc) x 16 k-subs = 1024 threads ---
            {
                const int sub  = tid & 15;
                const int tile = tid >> 4;            // 0..63
                const int n0   = (tile & 15) << 2;    // 0,4,...,60
                const int oc0  = (tile >> 4) << 1;    // 0,2,4,6

                float a00 = 0, a01 = 0, a10 = 0, a11 = 0;
                float a20 = 0, a21 = 0, a30 = 0, a31 = 0;
                #pragma unroll
                for (int it = 0; it < 16; it++) {
                    int k = sub + (it << 4);
                    float4 xv = *(const float4*)&xs[k * XT_STRIDE + n0];
                    float2 wv = *(const float2*)&wt[k * WT_STRIDE + oc0];
                    a00 = fmaf(xv.x, wv.x, a00);  a01 = fmaf(xv.x, wv.y, a01);
                    a10 = fmaf(xv.y, wv.x, a10);  a11 = fmaf(xv.y, wv.y, a11);
                    a20 = fmaf(xv.z, wv.x, a20);  a21 = fmaf(xv.z, wv.y, a21);
                    a30 = fmaf(xv.w, wv.x, a30);  a31 = fmaf(xv.w, wv.y, a31);
                }
                #pragma unroll
                for (int off = 8; off; off >>= 1) {
                    a00 += __shfl_down_sync(0xffffffffu, a00, off, 16);
                    a01 += __shfl_down_sync(0xffffffffu, a01, off, 16);
                    a10 += __shfl_down_sync(0xffffffffu, a10, off, 16);
                    a11 += __shfl_down_sync(0xffffffffu, a11, off, 16);
                    a20 += __shfl_down_sync(0xffffffffu, a20, off, 16);
                    a21 += __shfl_down_sync(0xffffffffu, a21, off, 16);
                    a30 += __shfl_down_sync(0xffffffffu, a30, off, 16);
                    a31 += __shfl_down_sync(0xffffffffu, a31, off, 16);
                }
                if (sub == 0) {
                    float bc0 = __ldg(&Bl[l][o0 + oc0]);
                    float bc1 = __ldg(&Bl[l][o0 + oc0 + 1]);
                    dotS[oc0 * 64 + n0 + 0] = a00 + bc0;
                    dotS[oc0 * 64 + n0 + 1] = a10 + bc0;
                    dotS[oc0 * 64 + n0 + 2] = a20 + bc0;
                    dotS[oc0 * 64 + n0 + 3] = a30 + bc0;
                    dotS[(oc0 + 1) * 64 + n0 + 0] = a01 + bc1;
                    dotS[(oc0 + 1) * 64 + n0 + 1] = a11 + bc1;
                    dotS[(oc0 + 1) * 64 + n0 + 2] = a21 + bc1;
                    dotS[(oc0 + 1) * 64 + n0 + 3] = a31 + bc1;
                }
            }
            __syncthreads();

            // --- BN stats: warps 0..7, one column each ---
            if (warp < 8) {
                float a = dotS[warp * 64 + lane];
                float c = dotS[warp * 64 + lane + 32];
                float s = a + c, q = a * a + c * c;
                #pragma unroll
                for (int off = 16; off; off >>= 1) {
                    s += __shfl_down_sync(0xffffffffu, s, off);
                    q += __shfl_down_sync(0xffffffffu, q, off);
                }
                if (lane == 0) {
                    float m = s * (1.0f / 64.0f);
                    float v = q * (1.0f / 64.0f) - m * m;
                    mS[warp] = m;
                    iS[warp] = rsqrtf(v + 1e-5f);
                }
            }
            __syncthreads();

            // --- BN + relu -> g_act transposed [o][n], coalesced ---
            if (tid < 512) {
                int oc = tid >> 6, n = tid & 63;
                int o  = o0 + oc;
                float d = dotS[oc * 64 + n];
                float h = __ldg(&Gl[l][o]) * (d - mS[oc]) * iS[oc] + __ldg(&El[l][o]);
                g_act[l & 1][o * 64 + n] = fmaxf(h, 0.0f);
            }

            if (l == 3) {
                if (bid != 0) { grid_barrier_arrive(4, GRIDB); return; }
                grid_barrier(4, GRIDB);
            } else {
                grid_barrier(1 + l, GRIDB);
            }
        }
    }

    // ------------------------------------------------------------------
    // Final FC (block 0): h = g_act[1] is [256 o][64 n]
    // ------------------------------------------------------------------
    {
        float* hs = sm;   // [256 o] x XT_STRIDE
        const float4* src = (const float4*)&g_act[1][0];
        for (int i = tid; i < 4096; i += THREADS) {
            float4 v = __ldcg(src + i);
            int o  = i >> 4;
            int n4 = (i & 15) << 2;
            *(float4*)&hs[o * XT_STRIDE + n4] = v;
        }
        __syncthreads();

        const int n   = tid >> 4;   // 0..63
        const int sub = tid & 15;
        float p = 0.0f;
        #pragma unroll
        for (int it = 0; it < 16; it++) {
            int o = sub + (it << 4);
            p = fmaf(hs[o * XT_STRIDE + n], __ldg(&w4[o]), p);
        }
        p += __shfl_down_sync(0xffffffffu, p, 8, 16);
        p += __shfl_down_sync(0xffffffffu, p, 4, 16);
        p += __shfl_down_sync(0xffffffffu, p, 2, 16);
        p += __shfl_down_sync(0xffffffffu, p, 1, 16);
        if (sub == 0) tc[n] = p + b4[0];
    }
}

// ---------------------------------------------------------------------------
extern "C" void kernel_launch(void* const* d_in, const int* in_sizes, int n_in,
                              void* d_out, int out_size)
{
    const float* xyz  = (const float*)d_in[0];
    const float* pts  = (const float*)d_in[1];
    const float* l3   = (const float*)d_in[2];
    const float* temp = (const float*)d_in[3];
    const float* w0   = (const float*)d_in[4];
    const float* b0   = (const float*)d_in[5];
    const float* g0   = (const float*)d_in[6];
    const float* e0   = (const float*)d_in[7];
    const float* w1   = (const float*)d_in[8];
    const float* b1   = (const float*)d_in[9];
    const float* g1   = (const float*)d_in[10];
    const float* e1   = (const float*)d_in[11];
    const float* w2   = (const float*)d_in[12];
    const float* b2   = (const float*)d_in[13];
    const float* g2   = (const float*)d_in[14];
    const float* e2   = (const float*)d_in[15];
    const float* w3   = (const float*)d_in[16];
    const float* b3   = (const float*)d_in[17];
    const float* g3   = (const float*)d_in[18];
    const float* e3   = (const float*)d_in[19];
    const float* w4   = (const float*)d_in[20];
    const float* b4   = (const float*)d_in[21];

    float* out   = (float*)d_out;
    float* tc    = out;
    float* tsys  = out + 64;
    float* opts  = out + 128;
    float* ocorr = out + 128 + (size_t)BB * CC * NN;

    cudaFuncSetAttribute(mega_kernel, cudaFuncAttributeMaxDynamicSharedMemorySize,
                         SMEM_BYTES);

    mega_kernel<<<GRIDN, THREADS, SMEM_BYTES>>>(
        xyz, pts, l3, temp,
        w0, b0, g0, e0,
        w1, b1, g1, e1,
        w2, b2, g2, e2,
        w3, b3, g3, e3,
        w4, b4,
        tc, tsys, opts, ocorr);

    (void)in_sizes; (void)n_in; (void)out_size;
}